// round 1
// baseline (speedup 1.0000x reference)
#include <cuda_runtime.h>
#include <math.h>
#include <float.h>

// ---------------------------------------------------------------------------
// Problem constants
// ---------------------------------------------------------------------------
#define M_BAG   100000
#define NFEAT   1024
#define NCOMP   512
#define NHID    256

// Output layout (flattened reference tuple, fp32)
#define OFF_ATT   0u
#define OFF_A     200000u
#define OFF_H     400000u
#define OFF_LAB   51600000u
#define OFF_IU    51600016u
#define OFF_IL    51600048u
#define OFF_SS    51600080u
#define OFF_YP    51600082u
#define OFF_YH    51600084u

// ---------------------------------------------------------------------------
// Device scratch (static globals: allocation-free per harness rules)
// ---------------------------------------------------------------------------
__device__ float g_t1[(size_t)M_BAG * NHID];
__device__ float g_t2[(size_t)M_BAG * NHID];
__device__ float g_AI[M_BAG];     // destructively consumed by top-8 (max)
__device__ float g_AI2[M_BAG];    // destructively consumed by bottom-8 (min)
__device__ float g_agg[2 * NCOMP];
__device__ int   g_topidx[16];    // [0..7] = top_pos_ids, [8..15] = top_neg_ids

// ---------------------------------------------------------------------------
// Tiled fp32 GEMM: C = act(A[MxK] @ B[KxN] + bias[N]), row-major.
// BM=128, BN=128, BK=8, 256 threads, 8x8 register micro-tile.
// ---------------------------------------------------------------------------
template<bool RELU>
__global__ __launch_bounds__(256)
void sgemm_bias(const float* __restrict__ A, const float* __restrict__ B,
                const float* __restrict__ bias, float* __restrict__ C,
                int M, int N, int K)
{
    const int BM = 128, BN = 128, BK = 8, TM = 8, TN = 8;
    __shared__ float As[BK][BM];
    __shared__ float Bs[BK][BN];

    const int tid = threadIdx.x;
    const int rowBase = blockIdx.y * BM;
    const int colBase = blockIdx.x * BN;

    // A-tile load mapping: 128x8 = 256 float4; thread i -> (row i/2, kcol (i&1)*4)
    const int aRow = tid >> 1;
    const int aCol = (tid & 1) * 4;
    // B-tile load mapping: 8x128 = 256 float4; thread i -> (krow i/32, col (i&31)*4)
    const int bRow = tid >> 5;
    const int bCol = (tid & 31) * 4;

    const int tx = tid % (BN / TN);   // 0..15
    const int ty = tid / (BN / TN);   // 0..15

    float acc[TM][TN];
    #pragma unroll
    for (int i = 0; i < TM; i++)
        #pragma unroll
        for (int j = 0; j < TN; j++) acc[i][j] = 0.0f;

    for (int k0 = 0; k0 < K; k0 += BK) {
        // load A tile (guard M)
        float4 av = make_float4(0.f, 0.f, 0.f, 0.f);
        int gr = rowBase + aRow;
        if (gr < M)
            av = *reinterpret_cast<const float4*>(A + (size_t)gr * K + k0 + aCol);
        As[aCol + 0][aRow] = av.x;
        As[aCol + 1][aRow] = av.y;
        As[aCol + 2][aRow] = av.z;
        As[aCol + 3][aRow] = av.w;

        // load B tile (N, K multiples of tile)
        float4 bv = *reinterpret_cast<const float4*>(
            B + (size_t)(k0 + bRow) * N + colBase + bCol);
        *reinterpret_cast<float4*>(&Bs[bRow][bCol]) = bv;

        __syncthreads();

        #pragma unroll
        for (int k = 0; k < BK; k++) {
            float ar[TM], br[TN];
            float4 a0 = *reinterpret_cast<const float4*>(&As[k][ty * TM]);
            float4 a1 = *reinterpret_cast<const float4*>(&As[k][ty * TM + 4]);
            ar[0]=a0.x; ar[1]=a0.y; ar[2]=a0.z; ar[3]=a0.w;
            ar[4]=a1.x; ar[5]=a1.y; ar[6]=a1.z; ar[7]=a1.w;
            float4 b0 = *reinterpret_cast<const float4*>(&Bs[k][tx * TN]);
            float4 b1 = *reinterpret_cast<const float4*>(&Bs[k][tx * TN + 4]);
            br[0]=b0.x; br[1]=b0.y; br[2]=b0.z; br[3]=b0.w;
            br[4]=b1.x; br[5]=b1.y; br[6]=b1.z; br[7]=b1.w;
            #pragma unroll
            for (int i = 0; i < TM; i++)
                #pragma unroll
                for (int j = 0; j < TN; j++)
                    acc[i][j] = fmaf(ar[i], br[j], acc[i][j]);
        }
        __syncthreads();
    }

    // epilogue: bias + activation + store
    #pragma unroll
    for (int i = 0; i < TM; i++) {
        int r = rowBase + ty * TM + i;
        if (r >= M) continue;
        #pragma unroll
        for (int j = 0; j < TN; j += 4) {
            int c = colBase + tx * TN + j;
            float4 v;
            v.x = acc[i][j + 0] + bias[c + 0];
            v.y = acc[i][j + 1] + bias[c + 1];
            v.z = acc[i][j + 2] + bias[c + 2];
            v.w = acc[i][j + 3] + bias[c + 3];
            if (RELU) {
                v.x = fmaxf(v.x, 0.f); v.y = fmaxf(v.y, 0.f);
                v.z = fmaxf(v.z, 0.f); v.w = fmaxf(v.w, 0.f);
            }
            *reinterpret_cast<float4*>(C + (size_t)r * N + c) = v;
        }
    }
}

// ---------------------------------------------------------------------------
// Zero the slide_agg accumulator
// ---------------------------------------------------------------------------
__global__ void zero_kernel()
{
    int t = threadIdx.x;
    if (t < 2 * NCOMP) g_agg[t] = 0.0f;
}

// ---------------------------------------------------------------------------
// Fused gated attention: warp per row.
// a = tanh(t1) * sigmoid(t2); att = a @ W3 + b3; A = softmax(att)
// Writes att_score, A, and A_I into two scratch copies for top-k.
// ---------------------------------------------------------------------------
__global__ __launch_bounds__(256)
void att_kernel(const float* __restrict__ W3, const float* __restrict__ b3,
                const int* __restrict__ slide_label,
                float* __restrict__ out_att, float* __restrict__ out_A)
{
    int warp = (blockIdx.x * blockDim.x + threadIdx.x) >> 5;
    int lane = threadIdx.x & 31;
    if (warp >= M_BAG) return;

    const float* t1 = g_t1 + (size_t)warp * NHID;
    const float* t2 = g_t2 + (size_t)warp * NHID;

    float acc0 = 0.f, acc1 = 0.f;
    #pragma unroll
    for (int j = lane; j < NHID; j += 32) {
        float v = tanhf(t1[j]) * (1.0f / (1.0f + expf(-t2[j])));
        acc0 = fmaf(v, W3[2 * j + 0], acc0);
        acc1 = fmaf(v, W3[2 * j + 1], acc1);
    }
    #pragma unroll
    for (int o = 16; o > 0; o >>= 1) {
        acc0 += __shfl_xor_sync(0xffffffffu, acc0, o);
        acc1 += __shfl_xor_sync(0xffffffffu, acc1, o);
    }
    if (lane == 0) {
        float s0 = acc0 + b3[0];
        float s1 = acc1 + b3[1];
        out_att[2 * warp + 0] = s0;
        out_att[2 * warp + 1] = s1;
        float m  = fmaxf(s0, s1);
        float e0 = expf(s0 - m), e1 = expf(s1 - m);
        float inv = 1.0f / (e0 + e1);
        float A0 = e0 * inv, A1 = e1 * inv;
        out_A[2 * warp + 0] = A0;
        out_A[2 * warp + 1] = A1;
        float ai = (slide_label[0] != 0) ? A1 : A0;
        g_AI[warp]  = ai;
        g_AI2[warp] = ai;
    }
}

// ---------------------------------------------------------------------------
// slide_agg[c][d] = sum_n A[n][c] * h[n][d]; register-accumulated per block
// over a 400-row chunk, then one atomicAdd per (thread, c, d-slot).
// ---------------------------------------------------------------------------
__global__ __launch_bounds__(256)
void agg_kernel(const float* __restrict__ Amat, const float* __restrict__ h)
{
    int tid = threadIdx.x;
    int d0 = tid, d1 = tid + 256;
    int r0 = blockIdx.x * 400;
    int r1 = min(r0 + 400, M_BAG);

    float a00 = 0.f, a01 = 0.f, a10 = 0.f, a11 = 0.f;
    for (int n = r0; n < r1; n++) {
        float A0 = Amat[2 * n + 0];
        float A1 = Amat[2 * n + 1];
        const float* hr = h + (size_t)n * NCOMP;
        float h0 = hr[d0];
        float h1 = hr[d1];
        a00 = fmaf(A0, h0, a00);
        a01 = fmaf(A1, h0, a01);
        a10 = fmaf(A0, h1, a10);
        a11 = fmaf(A1, h1, a11);
    }
    atomicAdd(&g_agg[d0],         a00);
    atomicAdd(&g_agg[NCOMP + d0], a01);
    atomicAdd(&g_agg[d1],         a10);
    atomicAdd(&g_agg[NCOMP + d1], a11);
}

// ---------------------------------------------------------------------------
// Iterative top-8 / bottom-8 with JAX tie-break (lower index wins).
// Single block, destructive on the two scratch copies.
// ---------------------------------------------------------------------------
__global__ __launch_bounds__(1024)
void topk_kernel()
{
    __shared__ float sv[1024];
    __shared__ int   si[1024];
    int tid = threadIdx.x;

    for (int phase = 0; phase < 2; phase++) {
        float* arr = phase ? g_AI2 : g_AI;
        for (int it = 0; it < 8; it++) {
            float bv = phase ? FLT_MAX : -FLT_MAX;
            int   bi = 0x7fffffff;
            for (int n = tid; n < M_BAG; n += 1024) {
                float v = arr[n];
                bool better = phase ? (v < bv || (v == bv && n < bi))
                                    : (v > bv || (v == bv && n < bi));
                if (better) { bv = v; bi = n; }
            }
            sv[tid] = bv; si[tid] = bi;
            __syncthreads();
            for (int s = 512; s > 0; s >>= 1) {
                if (tid < s) {
                    float ov = sv[tid + s]; int oi = si[tid + s];
                    bool better = phase ? (ov < sv[tid] || (ov == sv[tid] && oi < si[tid]))
                                        : (ov > sv[tid] || (ov == sv[tid] && oi < si[tid]));
                    if (better) { sv[tid] = ov; si[tid] = oi; }
                }
                __syncthreads();
            }
            if (tid == 0) {
                g_topidx[phase * 8 + it] = si[0];
                arr[si[0]] = phase ? FLT_MAX : -FLT_MAX;
            }
            __syncthreads();
        }
    }
}

// ---------------------------------------------------------------------------
// Tail: instance head (16x512 @ W_ins + softmax + labels) and slide
// score / Y_prob / Y_hat.
// ---------------------------------------------------------------------------
__global__ __launch_bounds__(1024)
void final_kernel(const float* __restrict__ W_ins, const float* __restrict__ b_ins,
                  const float* __restrict__ W_bag, const float* __restrict__ b_bag,
                  const float* __restrict__ h, float* __restrict__ out)
{
    __shared__ float s_logit[32];
    __shared__ float s_slide[2];
    int tid  = threadIdx.x;
    int lane = tid & 31;
    int w    = tid >> 5;

    // 32 warps: warps 0..31 compute ins_logit[row = w/2][class = w&1]
    {
        int row = w >> 1, c = w & 1;
        int idx = g_topidx[row];
        const float* hr = h + (size_t)idx * NCOMP;
        float acc = 0.f;
        for (int d = lane; d < NCOMP; d += 32)
            acc = fmaf(hr[d], W_ins[2 * d + c], acc);
        #pragma unroll
        for (int o = 16; o > 0; o >>= 1)
            acc += __shfl_xor_sync(0xffffffffu, acc, o);
        if (lane == 0) s_logit[row * 2 + c] = acc + b_ins[c];
    }

    // warps 0 & 1 also compute slide score (after the warp-reduce above,
    // reuse lanes; no dependence on s_logit)
    if (w < 2) {
        int c = w;
        float acc = 0.f;
        for (int d = lane; d < NCOMP; d += 32)
            acc = fmaf(g_agg[c * NCOMP + d], W_bag[d], acc);
        #pragma unroll
        for (int o = 16; o > 0; o >>= 1)
            acc += __shfl_xor_sync(0xffffffffu, acc, o);
        if (lane == 0) s_slide[c] = acc + b_bag[0];
    }
    __syncthreads();

    if (tid < 16) {
        float l0 = s_logit[tid * 2 + 0];
        float l1 = s_logit[tid * 2 + 1];
        out[OFF_IU + tid * 2 + 0] = l0;
        out[OFF_IU + tid * 2 + 1] = l1;
        float m = fmaxf(l0, l1);
        float e0 = expf(l0 - m), e1 = expf(l1 - m);
        float inv = 1.0f / (e0 + e1);
        out[OFF_IL + tid * 2 + 0] = e0 * inv;
        out[OFF_IL + tid * 2 + 1] = e1 * inv;
        out[OFF_LAB + tid] = (tid < 8) ? 1.0f : 0.0f;
    }
    if (tid == 0) {
        float s0 = s_slide[0], s1 = s_slide[1];
        out[OFF_SS + 0] = s0;
        out[OFF_SS + 1] = s1;
        float m = fmaxf(s0, s1);
        float e0 = expf(s0 - m), e1 = expf(s1 - m);
        float inv = 1.0f / (e0 + e1);
        out[OFF_YP + 0] = e0 * inv;
        out[OFF_YP + 1] = e1 * inv;
        out[OFF_YH] = (s1 > s0) ? 1.0f : 0.0f;   // argmax, first-max tie-break
    }
}

// ---------------------------------------------------------------------------
// kernel_launch
// ---------------------------------------------------------------------------
extern "C" void kernel_launch(void* const* d_in, const int* in_sizes, int n_in,
                              void* d_out, int out_size)
{
    const float* x   = (const float*)d_in[0];
    const int*   sl  = (const int*)  d_in[1];
    const float* Wc  = (const float*)d_in[2];
    const float* bc  = (const float*)d_in[3];
    const float* W1  = (const float*)d_in[4];
    const float* b1  = (const float*)d_in[5];
    const float* W2  = (const float*)d_in[6];
    const float* b2  = (const float*)d_in[7];
    const float* W3  = (const float*)d_in[8];
    const float* b3  = (const float*)d_in[9];
    const float* Wi  = (const float*)d_in[10];
    const float* bi  = (const float*)d_in[11];
    const float* Wb  = (const float*)d_in[12];
    const float* bb  = (const float*)d_in[13];

    float* out = (float*)d_out;
    float* h   = out + OFF_H;            // h written straight into its out slice

    void *t1p = nullptr, *t2p = nullptr;
    cudaGetSymbolAddress(&t1p, g_t1);
    cudaGetSymbolAddress(&t2p, g_t2);

    zero_kernel<<<1, 1024>>>();

    // h = relu(x @ Wc + bc)  : 100000 x 1024 x 512
    dim3 g1(NCOMP / 128, (M_BAG + 127) / 128);
    sgemm_bias<true><<<g1, 256>>>(x, Wc, bc, h, M_BAG, NCOMP, NFEAT);

    // t1 = h @ W1 + b1 ; t2 = h @ W2 + b2 : 100000 x 512 x 256
    dim3 g2(NHID / 128, (M_BAG + 127) / 128);
    sgemm_bias<false><<<g2, 256>>>(h, W1, b1, (float*)t1p, M_BAG, NHID, NCOMP);
    sgemm_bias<false><<<g2, 256>>>(h, W2, b2, (float*)t2p, M_BAG, NHID, NCOMP);

    // fused gate + attention head + softmax + A_I scatter
    att_kernel<<<(M_BAG * 32 + 255) / 256, 256>>>(W3, b3, sl,
                                                  out + OFF_ATT, out + OFF_A);

    // slide_agg = A^T @ h
    agg_kernel<<<(M_BAG + 399) / 400, 256>>>(out + OFF_A, h);

    // top-8 / bottom-8 of A_I
    topk_kernel<<<1, 1024>>>();

    // instance head + slide score tail
    final_kernel<<<1, 1024>>>(Wi, bi, Wb, bb, h, out);
}

// round 4
// speedup vs baseline: 5.6255x; 5.6255x over previous
#include <cuda_runtime.h>
#include <cuda_fp16.h>
#include <math.h>
#include <float.h>
#include <stdint.h>

// ---------------------------------------------------------------------------
// Problem constants
// ---------------------------------------------------------------------------
#define M_BAG   100000
#define M_PAD   100096          // 782 * 128
#define NFEAT   1024
#define NCOMP   512
#define NHID    256

// Output layout (flattened reference tuple, fp32)
#define OFF_ATT   0u
#define OFF_A     200000u
#define OFF_H     400000u
#define OFF_LAB   51600000u
#define OFF_IU    51600016u
#define OFF_IL    51600048u
#define OFF_SS    51600080u
#define OFF_YP    51600082u
#define OFF_YH    51600084u

// ---------------------------------------------------------------------------
// Device scratch (static globals; allocation-free per harness rules)
// ---------------------------------------------------------------------------
__device__ __half g_x16[(size_t)M_PAD * NFEAT];   // x in fp16 (padded rows zero)
__device__ __half g_hh[(size_t)M_PAD * NCOMP];    // h in fp16 (padded rows zero)
__device__ __half g_Wct[(size_t)NCOMP * NFEAT];   // Wc^T  [512][1024]
__device__ __half g_Wt12[(size_t)NCOMP * NCOMP];  // interleaved [W1|W2]^T [512][512]
__device__ float  g_att[2 * M_BAG];               // unnormalized att (atomic acc)
__device__ float  g_AI[M_BAG];
__device__ float  g_agg[2 * NCOMP];
__device__ int    g_topidx[16];
#define TK_BLOCKS 64
#define TK_CHUNK  1568
__device__ float  g_cmaxv[TK_BLOCKS * 8];
__device__ int    g_cmaxi[TK_BLOCKS * 8];
__device__ float  g_cminv[TK_BLOCKS * 8];
__device__ int    g_cmini[TK_BLOCKS * 8];

// ---------------------------------------------------------------------------
// PTX helpers (sm_80+ features only: mma.sync / ldmatrix / cp.async)
// ---------------------------------------------------------------------------
__device__ __forceinline__ uint32_t smem_u32(const void* p) {
    uint32_t a;
    asm("{ .reg .u64 t; cvta.to.shared.u64 t, %1; cvt.u32.u64 %0, t; }"
        : "=r"(a) : "l"(p));
    return a;
}

#define CPASYNC16(sa, gp) \
    asm volatile("cp.async.cg.shared.global [%0], [%1], 16;" \
                 :: "r"(sa), "l"(gp))
#define CPCOMMIT() asm volatile("cp.async.commit_group;")
template<int N> __device__ __forceinline__ void cp_wait() {
    asm volatile("cp.async.wait_group %0;" :: "n"(N));
}

__device__ __forceinline__ void ldsm4(uint32_t& r0, uint32_t& r1,
                                      uint32_t& r2, uint32_t& r3, uint32_t a) {
    asm volatile("ldmatrix.sync.aligned.m8n8.x4.shared.b16 {%0,%1,%2,%3}, [%4];"
                 : "=r"(r0), "=r"(r1), "=r"(r2), "=r"(r3) : "r"(a));
}

__device__ __forceinline__ void mma16816(float* c, const uint32_t* a,
                                         uint32_t b0, uint32_t b1) {
    asm volatile(
        "mma.sync.aligned.m16n8k16.row.col.f32.f16.f16.f32 "
        "{%0,%1,%2,%3}, {%4,%5,%6,%7}, {%8,%9}, {%0,%1,%2,%3};"
        : "+f"(c[0]), "+f"(c[1]), "+f"(c[2]), "+f"(c[3])
        : "r"(a[0]), "r"(a[1]), "r"(a[2]), "r"(a[3]), "r"(b0), "r"(b1));
}

// ---------------------------------------------------------------------------
// Prep: x -> fp16 (padded), Wc^T -> fp16, interleaved [W1|W2]^T -> fp16
// ---------------------------------------------------------------------------
__global__ void convert_x(const float* __restrict__ x)
{
    size_t gid = (size_t)blockIdx.x * blockDim.x + threadIdx.x;
    size_t base = gid * 8;
    if (base >= (size_t)M_PAD * NFEAT) return;
    uint4 v;
    if (base < (size_t)M_BAG * NFEAT) {
        const float4* p = reinterpret_cast<const float4*>(x + base);
        float4 a = p[0], b = p[1];
        __half2 h0 = __floats2half2_rn(a.x, a.y);
        __half2 h1 = __floats2half2_rn(a.z, a.w);
        __half2 h2 = __floats2half2_rn(b.x, b.y);
        __half2 h3 = __floats2half2_rn(b.z, b.w);
        v.x = *reinterpret_cast<uint32_t*>(&h0);
        v.y = *reinterpret_cast<uint32_t*>(&h1);
        v.z = *reinterpret_cast<uint32_t*>(&h2);
        v.w = *reinterpret_cast<uint32_t*>(&h3);
    } else v = make_uint4(0, 0, 0, 0);
    *reinterpret_cast<uint4*>(g_x16 + base) = v;
}

__global__ void prep_weights(const float* __restrict__ Wc,
                             const float* __restrict__ W1,
                             const float* __restrict__ W2)
{
    int i = blockIdx.x * blockDim.x + threadIdx.x;
    const int T1 = NCOMP * NFEAT;           // 524288
    if (i < T1) {
        int n = i / NFEAT, k = i % NFEAT;
        g_Wct[i] = __float2half_rn(Wc[(size_t)k * NCOMP + n]);
    }
    int i2 = i - T1;
    if (i2 >= 0 && i2 < NCOMP * NCOMP) {
        int rowN = i2 / NCOMP, k = i2 % NCOMP;
        int j = rowN >> 1, p = rowN & 1;
        const float* W = p ? W2 : W1;
        g_Wt12[i2] = __float2half_rn(W[(size_t)k * NHID + j]);
    }
}

__global__ void zero_init()
{
    int i = blockIdx.x * blockDim.x + threadIdx.x;
    if (i < 2 * M_BAG)  g_att[i] = 0.0f;
    if (i < 2 * NCOMP)  g_agg[i] = 0.0f;
}

// ---------------------------------------------------------------------------
// HMMA GEMM: BM=128, BN=256, BK=64, 256 threads (8 warps, 2x4, 64x64 tiles).
// Smem per stage: A 16KB + B 32KB, double-buffered cp.async, SW128 swizzle.
// MODE 0: h = relu(x16 @ Wct^T + bc), K=1024; writes h fp32 + fp16.
// MODE 1: t = hh @ Wt12^T (interleaved W1|W2), K=512; gate+W3 epilogue
//         accumulated into g_att with fp32 atomics.
// ---------------------------------------------------------------------------
template<int MODE>
__global__ void __launch_bounds__(256)
hmma_gemm(const float* __restrict__ bc,
          const float* __restrict__ b1, const float* __restrict__ b2,
          const float* __restrict__ W3, float* __restrict__ out)
{
    constexpr int K  = (MODE == 0) ? NFEAT : NCOMP;
    constexpr int NT = K / 64;
    extern __shared__ __align__(1024) char smem[];

    const int tid  = threadIdx.x;
    const int lane = tid & 31;
    const int wid  = tid >> 5;
    const int wm   = (wid >> 2) * 64;     // warp row offset in tile
    const int wn   = (wid & 3) * 64;      // warp col offset in tile
    const int rowBase = blockIdx.y * 128;
    const int colBase = blockIdx.x * 256;

    const uint32_t sbase = smem_u32(smem);
    const __half* Aglob = (MODE == 0) ? g_x16 : g_hh;
    const __half* Bglob = (MODE == 0) ? g_Wct : g_Wt12;

    // ldmatrix lane constants
    const int aRowOff = (lane & 7) + ((lane >> 3) & 1) * 8;
    const int aCk     = (lane >> 4) & 1;
    const int bRowOff = (lane & 7) + ((lane >> 4) & 1) * 8;
    const int bCk     = (lane >> 3) & 1;

    float acc[4][8][4];
    #pragma unroll
    for (int mi = 0; mi < 4; mi++)
        #pragma unroll
        for (int ni = 0; ni < 8; ni++)
            #pragma unroll
            for (int q = 0; q < 4; q++) acc[mi][ni][q] = 0.0f;

    // --- tile loader: stage into buf[stg]
    auto load_tiles = [&](int kt, int stg) {
        const uint32_t sA = sbase + stg * 49152;
        const uint32_t sB = sA + 16384;
        const __half* Ag = Aglob + (size_t)rowBase * K + kt * 64;
        const __half* Bg = Bglob + (size_t)colBase * K + kt * 64;
        #pragma unroll
        for (int i = 0; i < 4; i++) {
            int lin = tid + 256 * i;
            int row = lin >> 3, seg = lin & 7;
            uint32_t sa = sA + row * 128 + ((seg ^ (row & 7)) << 4);
            CPASYNC16(sa, Ag + (size_t)row * K + seg * 8);
        }
        #pragma unroll
        for (int i = 0; i < 8; i++) {
            int lin = tid + 256 * i;
            int row = lin >> 3, seg = lin & 7;
            uint32_t sa = sB + row * 128 + ((seg ^ (row & 7)) << 4);
            CPASYNC16(sa, Bg + (size_t)row * K + seg * 8);
        }
    };

    load_tiles(0, 0);
    CPCOMMIT();

    for (int kt = 0; kt < NT; kt++) {
        if (kt + 1 < NT) {
            load_tiles(kt + 1, (kt + 1) & 1);
            CPCOMMIT();
            cp_wait<1>();
        } else {
            cp_wait<0>();
        }
        __syncthreads();

        const uint32_t sA = sbase + (kt & 1) * 49152;
        const uint32_t sB = sA + 16384;

        #pragma unroll
        for (int ks = 0; ks < 4; ks++) {
            uint32_t a[4][4];
            #pragma unroll
            for (int mi = 0; mi < 4; mi++) {
                int row = wm + mi * 16 + aRowOff;
                uint32_t ad = sA + row * 128 +
                              (((ks * 2 + aCk) ^ (row & 7)) << 4);
                ldsm4(a[mi][0], a[mi][1], a[mi][2], a[mi][3], ad);
            }
            #pragma unroll
            for (int np = 0; np < 4; np++) {
                uint32_t b0, b1r, b2r, b3r;
                int row = wn + np * 16 + bRowOff;
                uint32_t bd = sB + row * 128 +
                              (((ks * 2 + bCk) ^ (row & 7)) << 4);
                ldsm4(b0, b1r, b2r, b3r, bd);
                #pragma unroll
                for (int mi = 0; mi < 4; mi++) {
                    mma16816(acc[mi][2 * np + 0], a[mi], b0, b1r);
                    mma16816(acc[mi][2 * np + 1], a[mi], b2r, b3r);
                }
            }
        }
        __syncthreads();
    }

    // ------------------------ epilogue ------------------------
    const int qrow = lane >> 2;          // 0..7
    const int qcol = (lane & 3) * 2;     // 0,2,4,6

    if (MODE == 0) {
        float* h32 = out + OFF_H;
        float2 bias_v[8];
        #pragma unroll
        for (int ni = 0; ni < 8; ni++) {
            int col = colBase + wn + ni * 8 + qcol;
            bias_v[ni] = *reinterpret_cast<const float2*>(bc + col);
        }
        #pragma unroll
        for (int mi = 0; mi < 4; mi++) {
            int r0 = rowBase + wm + mi * 16 + qrow;
            int r1 = r0 + 8;
            #pragma unroll
            for (int ni = 0; ni < 8; ni++) {
                int col = colBase + wn + ni * 8 + qcol;
                float v0 = fmaxf(acc[mi][ni][0] + bias_v[ni].x, 0.f);
                float v1 = fmaxf(acc[mi][ni][1] + bias_v[ni].y, 0.f);
                float v2 = fmaxf(acc[mi][ni][2] + bias_v[ni].x, 0.f);
                float v3 = fmaxf(acc[mi][ni][3] + bias_v[ni].y, 0.f);
                if (r0 < M_BAG) {
                    *reinterpret_cast<float2*>(h32 + (size_t)r0 * NCOMP + col)
                        = make_float2(v0, v1);
                    __half2 p = __floats2half2_rn(v0, v1);
                    *reinterpret_cast<__half2*>(g_hh + (size_t)r0 * NCOMP + col) = p;
                }
                if (r1 < M_BAG) {
                    *reinterpret_cast<float2*>(h32 + (size_t)r1 * NCOMP + col)
                        = make_float2(v2, v3);
                    __half2 p = __floats2half2_rn(v2, v3);
                    *reinterpret_cast<__half2*>(g_hh + (size_t)r1 * NCOMP + col) = p;
                }
            }
        }
    } else {
        // gate + a@W3, quad-reduced atomics
        float b1v[8], b2v[8], w3x[8], w3y[8];
        #pragma unroll
        for (int ni = 0; ni < 8; ni++) {
            int j = (colBase + wn + ni * 8 + qcol) >> 1;
            b1v[ni] = b1[j];
            b2v[ni] = b2[j];
            float2 w = reinterpret_cast<const float2*>(W3)[j];
            w3x[ni] = w.x; w3y[ni] = w.y;
        }
        #pragma unroll
        for (int mi = 0; mi < 4; mi++) {
            int r0 = rowBase + wm + mi * 16 + qrow;
            int r1 = r0 + 8;
            float s00 = 0.f, s01 = 0.f, s10 = 0.f, s11 = 0.f;
            #pragma unroll
            for (int ni = 0; ni < 8; ni++) {
                float t1 = acc[mi][ni][0] + b1v[ni];
                float t2 = acc[mi][ni][1] + b2v[ni];
                float a0 = tanhf(t1) * (1.0f / (1.0f + expf(-t2)));
                s00 = fmaf(a0, w3x[ni], s00);
                s01 = fmaf(a0, w3y[ni], s01);
                float u1 = acc[mi][ni][2] + b1v[ni];
                float u2 = acc[mi][ni][3] + b2v[ni];
                float a1 = tanhf(u1) * (1.0f / (1.0f + expf(-u2)));
                s10 = fmaf(a1, w3x[ni], s10);
                s11 = fmaf(a1, w3y[ni], s11);
            }
            #pragma unroll
            for (int o = 1; o <= 2; o <<= 1) {
                s00 += __shfl_xor_sync(0xffffffffu, s00, o);
                s01 += __shfl_xor_sync(0xffffffffu, s01, o);
                s10 += __shfl_xor_sync(0xffffffffu, s10, o);
                s11 += __shfl_xor_sync(0xffffffffu, s11, o);
            }
            if ((lane & 3) == 0) {
                if (r0 < M_BAG) {
                    atomicAdd(&g_att[2 * r0 + 0], s00);
                    atomicAdd(&g_att[2 * r0 + 1], s01);
                }
                if (r1 < M_BAG) {
                    atomicAdd(&g_att[2 * r1 + 0], s10);
                    atomicAdd(&g_att[2 * r1 + 1], s11);
                }
            }
        }
    }
}

// ---------------------------------------------------------------------------
// att finish: add b3, softmax, write att_score / A / A_I
// ---------------------------------------------------------------------------
__global__ void att_finish(const float* __restrict__ b3, const int* __restrict__ sl,
                           float* __restrict__ out)
{
    int r = blockIdx.x * blockDim.x + threadIdx.x;
    if (r >= M_BAG) return;
    float s0 = g_att[2 * r + 0] + b3[0];
    float s1 = g_att[2 * r + 1] + b3[1];
    out[OFF_ATT + 2 * r + 0] = s0;
    out[OFF_ATT + 2 * r + 1] = s1;
    float m  = fmaxf(s0, s1);
    float e0 = expf(s0 - m), e1 = expf(s1 - m);
    float inv = 1.0f / (e0 + e1);
    float A0 = e0 * inv, A1 = e1 * inv;
    out[OFF_A + 2 * r + 0] = A0;
    out[OFF_A + 2 * r + 1] = A1;
    g_AI[r] = (sl[0] != 0) ? A1 : A0;
}

// ---------------------------------------------------------------------------
// slide_agg = A^T @ h (h from fp16 copy), per-block partials + atomics
// ---------------------------------------------------------------------------
__global__ __launch_bounds__(256)
void agg_kernel(const float* __restrict__ Amat)
{
    int tid = threadIdx.x;
    int r0 = blockIdx.x * 256;
    int r1 = min(r0 + 256, M_BAG);

    float a00 = 0.f, a01 = 0.f, a10 = 0.f, a11 = 0.f;
    const __half2* hv2 = reinterpret_cast<const __half2*>(g_hh);
    for (int n = r0; n < r1; n++) {
        float2 Av = reinterpret_cast<const float2*>(Amat)[n];
        __half2 hp = hv2[(size_t)n * 256 + tid];
        float h0 = __low2float(hp), h1 = __high2float(hp);
        a00 = fmaf(Av.x, h0, a00);
        a01 = fmaf(Av.y, h0, a01);
        a10 = fmaf(Av.x, h1, a10);
        a11 = fmaf(Av.y, h1, a11);
    }
    int d0 = tid * 2, d1 = tid * 2 + 1;
    atomicAdd(&g_agg[d0],         a00);
    atomicAdd(&g_agg[NCOMP + d0], a01);
    atomicAdd(&g_agg[d1],         a10);
    atomicAdd(&g_agg[NCOMP + d1], a11);
}

// ---------------------------------------------------------------------------
// Two-stage top-8 / bottom-8, JAX tie-break (lower index wins)
// ---------------------------------------------------------------------------
__global__ __launch_bounds__(256)
void topk_stage1()
{
    __shared__ float svmax[TK_CHUNK];
    __shared__ float svmin[TK_CHUNK];
    __shared__ float rv[256];
    __shared__ int   ri[256];
    int tid  = threadIdx.x;
    int base = blockIdx.x * TK_CHUNK;

    for (int i = tid; i < TK_CHUNK; i += 256) {
        int g = base + i;
        float v = (g < M_BAG) ? g_AI[g] : 0.0f;
        svmax[i] = (g < M_BAG) ? v : -FLT_MAX;
        svmin[i] = (g < M_BAG) ? v :  FLT_MAX;
    }
    __syncthreads();

    for (int pass = 0; pass < 8; pass++) {
        float bv = -FLT_MAX; int bi = 0x7fffffff;
        for (int i = tid; i < TK_CHUNK; i += 256) {
            float v = svmax[i]; int g = base + i;
            if (v > bv || (v == bv && g < bi)) { bv = v; bi = g; }
        }
        rv[tid] = bv; ri[tid] = bi;
        __syncthreads();
        for (int s = 128; s > 0; s >>= 1) {
            if (tid < s) {
                float ov = rv[tid + s]; int oi = ri[tid + s];
                if (ov > rv[tid] || (ov == rv[tid] && oi < ri[tid])) { rv[tid] = ov; ri[tid] = oi; }
            }
            __syncthreads();
        }
        if (tid == 0) {
            g_cmaxv[blockIdx.x * 8 + pass] = rv[0];
            g_cmaxi[blockIdx.x * 8 + pass] = ri[0];
            svmax[ri[0] - base] = -FLT_MAX;
        }
        __syncthreads();
    }
    for (int pass = 0; pass < 8; pass++) {
        float bv = FLT_MAX; int bi = 0x7fffffff;
        for (int i = tid; i < TK_CHUNK; i += 256) {
            float v = svmin[i]; int g = base + i;
            if (v < bv || (v == bv && g < bi)) { bv = v; bi = g; }
        }
        rv[tid] = bv; ri[tid] = bi;
        __syncthreads();
        for (int s = 128; s > 0; s >>= 1) {
            if (tid < s) {
                float ov = rv[tid + s]; int oi = ri[tid + s];
                if (ov < rv[tid] || (ov == rv[tid] && oi < ri[tid])) { rv[tid] = ov; ri[tid] = oi; }
            }
            __syncthreads();
        }
        if (tid == 0) {
            g_cminv[blockIdx.x * 8 + pass] = rv[0];
            g_cmini[blockIdx.x * 8 + pass] = ri[0];
            svmin[ri[0] - base] = FLT_MAX;
        }
        __syncthreads();
    }
}

__global__ __launch_bounds__(512)
void topk_stage2()
{
    __shared__ float sv[512];
    __shared__ int   si[512];
    __shared__ float rv[512];
    __shared__ int   ri[512];
    int tid = threadIdx.x;

    sv[tid] = g_cmaxv[tid];
    si[tid] = g_cmaxi[tid];
    __syncthreads();
    for (int pass = 0; pass < 8; pass++) {
        rv[tid] = sv[tid]; ri[tid] = si[tid];
        __syncthreads();
        for (int s = 256; s > 0; s >>= 1) {
            if (tid < s) {
                float ov = rv[tid + s]; int oi = ri[tid + s];
                if (ov > rv[tid] || (ov == rv[tid] && oi < ri[tid])) { rv[tid] = ov; ri[tid] = oi; }
            }
            __syncthreads();
        }
        if (tid == 0) g_topidx[pass] = ri[0];
        if (si[tid] == ri[0]) { sv[tid] = -FLT_MAX; si[tid] = 0x7fffffff; }
        __syncthreads();
    }
    sv[tid] = g_cminv[tid];
    si[tid] = g_cmini[tid];
    __syncthreads();
    for (int pass = 0; pass < 8; pass++) {
        rv[tid] = sv[tid]; ri[tid] = si[tid];
        __syncthreads();
        for (int s = 256; s > 0; s >>= 1) {
            if (tid < s) {
                float ov = rv[tid + s]; int oi = ri[tid + s];
                if (ov < rv[tid] || (ov == rv[tid] && oi < ri[tid])) { rv[tid] = ov; ri[tid] = oi; }
            }
            __syncthreads();
        }
        if (tid == 0) g_topidx[8 + pass] = ri[0];
        if (si[tid] == ri[0]) { sv[tid] = FLT_MAX; si[tid] = 0x7fffffff; }
        __syncthreads();
    }
}

// ---------------------------------------------------------------------------
// Tail: instance head + slide score
// ---------------------------------------------------------------------------
__global__ __launch_bounds__(1024)
void final_kernel(const float* __restrict__ W_ins, const float* __restrict__ b_ins,
                  const float* __restrict__ W_bag, const float* __restrict__ b_bag,
                  const float* __restrict__ h, float* __restrict__ out)
{
    __shared__ float s_logit[32];
    __shared__ float s_slide[2];
    int tid  = threadIdx.x;
    int lane = tid & 31;
    int w    = tid >> 5;

    {
        int row = w >> 1, c = w & 1;
        int idx = g_topidx[row];
        const float* hr = h + (size_t)idx * NCOMP;
        float acc = 0.f;
        for (int d = lane; d < NCOMP; d += 32)
            acc = fmaf(hr[d], W_ins[2 * d + c], acc);
        #pragma unroll
        for (int o = 16; o > 0; o >>= 1)
            acc += __shfl_xor_sync(0xffffffffu, acc, o);
        if (lane == 0) s_logit[row * 2 + c] = acc + b_ins[c];
    }
    if (w < 2) {
        int c = w;
        float acc = 0.f;
        for (int d = lane; d < NCOMP; d += 32)
            acc = fmaf(g_agg[c * NCOMP + d], W_bag[d], acc);
        #pragma unroll
        for (int o = 16; o > 0; o >>= 1)
            acc += __shfl_xor_sync(0xffffffffu, acc, o);
        if (lane == 0) s_slide[c] = acc + b_bag[0];
    }
    __syncthreads();

    if (tid < 16) {
        float l0 = s_logit[tid * 2 + 0];
        float l1 = s_logit[tid * 2 + 1];
        out[OFF_IU + tid * 2 + 0] = l0;
        out[OFF_IU + tid * 2 + 1] = l1;
        float m = fmaxf(l0, l1);
        float e0 = expf(l0 - m), e1 = expf(l1 - m);
        float inv = 1.0f / (e0 + e1);
        out[OFF_IL + tid * 2 + 0] = e0 * inv;
        out[OFF_IL + tid * 2 + 1] = e1 * inv;
        out[OFF_LAB + tid] = (tid < 8) ? 1.0f : 0.0f;
    }
    if (tid == 0) {
        float s0 = s_slide[0], s1 = s_slide[1];
        out[OFF_SS + 0] = s0;
        out[OFF_SS + 1] = s1;
        float m = fmaxf(s0, s1);
        float e0 = expf(s0 - m), e1 = expf(s1 - m);
        float inv = 1.0f / (e0 + e1);
        out[OFF_YP + 0] = e0 * inv;
        out[OFF_YP + 1] = e1 * inv;
        out[OFF_YH] = (s1 > s0) ? 1.0f : 0.0f;
    }
}

// ---------------------------------------------------------------------------
// kernel_launch
// ---------------------------------------------------------------------------
extern "C" void kernel_launch(void* const* d_in, const int* in_sizes, int n_in,
                              void* d_out, int out_size)
{
    const float* x   = (const float*)d_in[0];
    const int*   sl  = (const int*)  d_in[1];
    const float* Wc  = (const float*)d_in[2];
    const float* bc  = (const float*)d_in[3];
    const float* W1  = (const float*)d_in[4];
    const float* b1  = (const float*)d_in[5];
    const float* W2  = (const float*)d_in[6];
    const float* b2  = (const float*)d_in[7];
    const float* W3  = (const float*)d_in[8];
    const float* b3  = (const float*)d_in[9];
    const float* Wi  = (const float*)d_in[10];
    const float* bi  = (const float*)d_in[11];
    const float* Wb  = (const float*)d_in[12];
    const float* bb  = (const float*)d_in[13];

    float* out = (float*)d_out;
    float* h   = out + OFF_H;

    const int SMEM = 2 * 49152;   // 96KB dynamic
    cudaFuncSetAttribute(hmma_gemm<0>, cudaFuncAttributeMaxDynamicSharedMemorySize, SMEM);
    cudaFuncSetAttribute(hmma_gemm<1>, cudaFuncAttributeMaxDynamicSharedMemorySize, SMEM);

    convert_x<<<(int)(((size_t)M_PAD * NFEAT / 8 + 255) / 256), 256>>>(x);
    prep_weights<<<3072, 256>>>(Wc, W1, W2);
    zero_init<<<(2 * M_BAG + 255) / 256, 256>>>();

    dim3 g1(2, M_PAD / 128);   // N=512 in 2 column blocks of 256
    hmma_gemm<0><<<g1, 256, SMEM>>>(bc, b1, b2, W3, out);
    hmma_gemm<1><<<g1, 256, SMEM>>>(bc, b1, b2, W3, out);

    att_finish<<<(M_BAG + 255) / 256, 256>>>(b3, sl, out);

    agg_kernel<<<(M_BAG + 255) / 256, 256>>>(out + OFF_A);

    topk_stage1<<<TK_BLOCKS, 256>>>();
    topk_stage2<<<1, 512>>>();

    final_kernel<<<1, 1024>>>(Wi, bi, Wb, bb, h, out);
}

// round 5
// speedup vs baseline: 5.8065x; 1.0322x over previous
#include <cuda_runtime.h>
#include <cuda_fp16.h>
#include <math.h>
#include <float.h>
#include <stdint.h>

// ---------------------------------------------------------------------------
// Problem constants
// ---------------------------------------------------------------------------
#define M_BAG   100000
#define M_PAD   100096          // 782 * 128 = 1564 * 64
#define NFEAT   1024
#define NCOMP   512
#define NHID    256

// Output layout (flattened reference tuple, fp32)
#define OFF_ATT   0u
#define OFF_A     200000u
#define OFF_H     400000u
#define OFF_LAB   51600000u
#define OFF_IU    51600016u
#define OFF_IL    51600048u
#define OFF_SS    51600080u
#define OFF_YP    51600082u
#define OFF_YH    51600084u

// ---------------------------------------------------------------------------
// Device scratch (static globals; allocation-free per harness rules)
// ---------------------------------------------------------------------------
__device__ __half g_hh[(size_t)M_PAD * NCOMP];    // h in fp16 (padded rows zero)
__device__ __half g_Wct[(size_t)NCOMP * NFEAT];   // Wc^T  [512][1024]
__device__ __half g_Wt12[(size_t)NCOMP * NCOMP];  // interleaved [W1|W2]^T [512][512]
__device__ float  g_att[2 * M_BAG];               // unnormalized att (atomic acc)
__device__ float  g_AI[M_BAG];
__device__ float  g_agg[2 * NCOMP];
__device__ int    g_topidx[16];
#define TK_BLOCKS 64
#define TK_CHUNK  1568
__device__ float  g_cmaxv[TK_BLOCKS * 8];
__device__ int    g_cmaxi[TK_BLOCKS * 8];
__device__ float  g_cminv[TK_BLOCKS * 8];
__device__ int    g_cmini[TK_BLOCKS * 8];

// ---------------------------------------------------------------------------
// PTX helpers (sm_80+ features only: mma.sync / ldmatrix / cp.async)
// ---------------------------------------------------------------------------
__device__ __forceinline__ uint32_t smem_u32(const void* p) {
    uint32_t a;
    asm("{ .reg .u64 t; cvta.to.shared.u64 t, %1; cvt.u32.u64 %0, t; }"
        : "=r"(a) : "l"(p));
    return a;
}

#define CPASYNC16(sa, gp) \
    asm volatile("cp.async.cg.shared.global [%0], [%1], 16;" \
                 :: "r"(sa), "l"(gp))
#define CPCOMMIT() asm volatile("cp.async.commit_group;")
template<int N> __device__ __forceinline__ void cp_wait() {
    asm volatile("cp.async.wait_group %0;" :: "n"(N));
}

__device__ __forceinline__ void ldsm4(uint32_t& r0, uint32_t& r1,
                                      uint32_t& r2, uint32_t& r3, uint32_t a) {
    asm volatile("ldmatrix.sync.aligned.m8n8.x4.shared.b16 {%0,%1,%2,%3}, [%4];"
                 : "=r"(r0), "=r"(r1), "=r"(r2), "=r"(r3) : "r"(a));
}

__device__ __forceinline__ void mma16816(float* c, const uint32_t* a,
                                         uint32_t b0, uint32_t b1) {
    asm volatile(
        "mma.sync.aligned.m16n8k16.row.col.f32.f16.f16.f32 "
        "{%0,%1,%2,%3}, {%4,%5,%6,%7}, {%8,%9}, {%0,%1,%2,%3};"
        : "+f"(c[0]), "+f"(c[1]), "+f"(c[2]), "+f"(c[3])
        : "r"(a[0]), "r"(a[1]), "r"(a[2]), "r"(a[3]), "r"(b0), "r"(b1));
}

// ---------------------------------------------------------------------------
// Prep: Wc^T -> fp16, interleaved [W1|W2]^T -> fp16
// ---------------------------------------------------------------------------
__global__ void prep_weights(const float* __restrict__ Wc,
                             const float* __restrict__ W1,
                             const float* __restrict__ W2)
{
    int i = blockIdx.x * blockDim.x + threadIdx.x;
    const int T1 = NCOMP * NFEAT;           // 524288
    if (i < T1) {
        int n = i / NFEAT, k = i % NFEAT;
        g_Wct[i] = __float2half_rn(Wc[(size_t)k * NCOMP + n]);
    }
    int i2 = i - T1;
    if (i2 >= 0 && i2 < NCOMP * NCOMP) {
        int rowN = i2 / NCOMP, k = i2 % NCOMP;
        int j = rowN >> 1, p = rowN & 1;
        const float* W = p ? W2 : W1;
        g_Wt12[i2] = __float2half_rn(W[(size_t)k * NHID + j]);
    }
}

__global__ void zero_init()
{
    int i = blockIdx.x * blockDim.x + threadIdx.x;
    if (i < 2 * M_BAG)  g_att[i] = 0.0f;
    if (i < 2 * NCOMP)  g_agg[i] = 0.0f;
}

// ---------------------------------------------------------------------------
// HMMA GEMM, 256 threads (8 warps), double-buffered smem, SW128 swizzle.
// MODE 0: BM=128, BN=256, K=1024, grid (2, 782).
//         h = relu(x @ Wc + bc). A loaded fp32 via LDG, converted to fp16
//         in registers, STS'd (conversion fused; no separate pass).
//         Epilogue writes h fp32 (out) + fp16 (g_hh).
// MODE 1: BM=64, BN=512, K=512, grid (1, 1564); A = g_hh read ONCE.
//         t = h @ [W1|W2] interleaved; epilogue computes
//         a = tanh(t1)*sigmoid(t2) and atomically adds a@W3 into g_att.
// ---------------------------------------------------------------------------
template<int MODE>
__global__ void __launch_bounds__(256)
hmma_gemm(const float* __restrict__ x, const float* __restrict__ bc,
          const float* __restrict__ b1, const float* __restrict__ b2,
          const float* __restrict__ W3, float* __restrict__ out)
{
    constexpr int K      = (MODE == 0) ? NFEAT : NCOMP;
    constexpr int NT     = K / 64;
    constexpr int BM     = (MODE == 0) ? 128 : 64;
    constexpr int BN     = (MODE == 0) ? 256 : 512;
    constexpr int ABYTES = BM * 128;                // fp16 tile bytes
    constexpr int STRIDE = ABYTES + BN * 128;       // stage stride
    constexpr int BCH    = BN / 32;                 // B 16B-chunks per thread (8/16)

    extern __shared__ __align__(1024) char smem[];

    const int tid  = threadIdx.x;
    const int lane = tid & 31;
    const int wid  = tid >> 5;
    const int wm   = (MODE == 0) ? ((wid >> 2) * 64) : 0;
    const int wn   = (MODE == 0) ? ((wid & 3) * 64) : (wid * 64);
    const int rowBase = blockIdx.y * BM;
    const int colBase = (MODE == 0) ? (blockIdx.x * 256) : 0;

    const uint32_t sbase = smem_u32(smem);
    const __half* Bglob = (MODE == 0) ? g_Wct : g_Wt12;

    // ldmatrix lane constants
    const int aRowOff = (lane & 7) + ((lane >> 3) & 1) * 8;
    const int aCk     = (lane >> 4) & 1;
    const int bRowOff = (lane & 7) + ((lane >> 4) & 1) * 8;
    const int bCk     = (lane >> 3) & 1;

    float acc[4][8][4];
    #pragma unroll
    for (int mi = 0; mi < 4; mi++)
        #pragma unroll
        for (int ni = 0; ni < 8; ni++)
            #pragma unroll
            for (int q = 0; q < 4; q++) acc[mi][ni][q] = 0.0f;

    // ---- loaders -----------------------------------------------------------
    // B tiles via cp.async (fp16 source)
    auto load_b = [&](int kt, int stg) {
        const uint32_t sB = sbase + stg * STRIDE + ABYTES;
        const __half* Bg = Bglob + (size_t)colBase * K + kt * 64;
        #pragma unroll
        for (int i = 0; i < BCH; i++) {
            int lin = tid + 256 * i;
            int row = lin >> 3, seg = lin & 7;
            uint32_t sa = sB + row * 128 + ((seg ^ (row & 7)) << 4);
            CPASYNC16(sa, Bg + (size_t)row * K + seg * 8);
        }
    };

    float4 areg[8];                    // MODE 0: fp32 A prefetch (4 chunks x 2)
    // MODE 0: LDG fp32 A tile into registers
    auto ldg_a = [&](int kt) {
        #pragma unroll
        for (int i = 0; i < 4; i++) {
            int lin = tid + 256 * i;
            int row = lin >> 3, seg = lin & 7;
            int gr  = rowBase + row;
            if (gr < M_BAG) {
                const float4* p = reinterpret_cast<const float4*>(
                    x + (size_t)gr * K + kt * 64 + seg * 8);
                areg[2 * i]     = p[0];
                areg[2 * i + 1] = p[1];
            } else {
                areg[2 * i]     = make_float4(0.f, 0.f, 0.f, 0.f);
                areg[2 * i + 1] = make_float4(0.f, 0.f, 0.f, 0.f);
            }
        }
    };
    // MODE 0: convert + STS the prefetched tile
    auto sts_a = [&](int stg) {
        char* sA = smem + stg * STRIDE;
        #pragma unroll
        for (int i = 0; i < 4; i++) {
            int lin = tid + 256 * i;
            int row = lin >> 3, seg = lin & 7;
            float4 a = areg[2 * i], b = areg[2 * i + 1];
            __half2 h0 = __floats2half2_rn(a.x, a.y);
            __half2 h1 = __floats2half2_rn(a.z, a.w);
            __half2 h2 = __floats2half2_rn(b.x, b.y);
            __half2 h3 = __floats2half2_rn(b.z, b.w);
            uint4 v;
            v.x = *reinterpret_cast<uint32_t*>(&h0);
            v.y = *reinterpret_cast<uint32_t*>(&h1);
            v.z = *reinterpret_cast<uint32_t*>(&h2);
            v.w = *reinterpret_cast<uint32_t*>(&h3);
            *reinterpret_cast<uint4*>(sA + row * 128 + ((seg ^ (row & 7)) << 4)) = v;
        }
    };
    // MODE 1: A tile via cp.async from g_hh (fp16)
    auto cp_a = [&](int kt, int stg) {
        const uint32_t sA = sbase + stg * STRIDE;
        const __half* Ag = g_hh + (size_t)rowBase * K + kt * 64;
        #pragma unroll
        for (int i = 0; i < 2; i++) {
            int lin = tid + 256 * i;
            int row = lin >> 3, seg = lin & 7;
            uint32_t sa = sA + row * 128 + ((seg ^ (row & 7)) << 4);
            CPASYNC16(sa, Ag + (size_t)row * K + seg * 8);
        }
    };

    // ---- prologue ----------------------------------------------------------
    if (MODE == 0) {
        ldg_a(0);
        load_b(0, 0);
        CPCOMMIT();
        sts_a(0);
    } else {
        cp_a(0, 0);
        load_b(0, 0);
        CPCOMMIT();
    }

    // ---- main loop ---------------------------------------------------------
    for (int kt = 0; kt < NT; kt++) {
        const bool more = (kt + 1 < NT);
        if (more) {
            if (MODE == 0) {
                ldg_a(kt + 1);                 // fp32 prefetch into regs
                load_b(kt + 1, (kt + 1) & 1);
            } else {
                cp_a(kt + 1, (kt + 1) & 1);
                load_b(kt + 1, (kt + 1) & 1);
            }
            CPCOMMIT();
            cp_wait<1>();
        } else {
            cp_wait<0>();
        }
        __syncthreads();

        const uint32_t sA = sbase + (kt & 1) * STRIDE;
        const uint32_t sB = sA + ABYTES;

        #pragma unroll
        for (int ks = 0; ks < 4; ks++) {
            uint32_t a[4][4];
            #pragma unroll
            for (int mi = 0; mi < 4; mi++) {
                int row = wm + mi * 16 + aRowOff;
                uint32_t ad = sA + row * 128 +
                              (((ks * 2 + aCk) ^ (row & 7)) << 4);
                ldsm4(a[mi][0], a[mi][1], a[mi][2], a[mi][3], ad);
            }
            #pragma unroll
            for (int np = 0; np < 4; np++) {
                uint32_t b0, b1r, b2r, b3r;
                int row = wn + np * 16 + bRowOff;
                uint32_t bd = sB + row * 128 +
                              (((ks * 2 + bCk) ^ (row & 7)) << 4);
                ldsm4(b0, b1r, b2r, b3r, bd);
                #pragma unroll
                for (int mi = 0; mi < 4; mi++) {
                    mma16816(acc[mi][2 * np + 0], a[mi], b0, b1r);
                    mma16816(acc[mi][2 * np + 1], a[mi], b2r, b3r);
                }
            }
        }

        if (MODE == 0 && more) sts_a((kt + 1) & 1);
        __syncthreads();
    }

    // ------------------------ epilogue ------------------------
    const int qrow = lane >> 2;          // 0..7
    const int qcol = (lane & 3) * 2;     // 0,2,4,6

    if (MODE == 0) {
        float* h32 = out + OFF_H;
        float2 bias_v[8];
        #pragma unroll
        for (int ni = 0; ni < 8; ni++) {
            int col = colBase + wn + ni * 8 + qcol;
            bias_v[ni] = *reinterpret_cast<const float2*>(bc + col);
        }
        #pragma unroll
        for (int mi = 0; mi < 4; mi++) {
            int r0 = rowBase + wm + mi * 16 + qrow;
            int r1 = r0 + 8;
            #pragma unroll
            for (int ni = 0; ni < 8; ni++) {
                int col = colBase + wn + ni * 8 + qcol;
                float v0 = fmaxf(acc[mi][ni][0] + bias_v[ni].x, 0.f);
                float v1 = fmaxf(acc[mi][ni][1] + bias_v[ni].y, 0.f);
                float v2 = fmaxf(acc[mi][ni][2] + bias_v[ni].x, 0.f);
                float v3 = fmaxf(acc[mi][ni][3] + bias_v[ni].y, 0.f);
                if (r0 < M_BAG) {
                    *reinterpret_cast<float2*>(h32 + (size_t)r0 * NCOMP + col)
                        = make_float2(v0, v1);
                    __half2 p = __floats2half2_rn(v0, v1);
                    *reinterpret_cast<__half2*>(g_hh + (size_t)r0 * NCOMP + col) = p;
                }
                if (r1 < M_BAG) {
                    *reinterpret_cast<float2*>(h32 + (size_t)r1 * NCOMP + col)
                        = make_float2(v2, v3);
                    __half2 p = __floats2half2_rn(v2, v3);
                    *reinterpret_cast<__half2*>(g_hh + (size_t)r1 * NCOMP + col) = p;
                }
            }
        }
    } else {
        // gate + a@W3, quad-reduced atomics
        float b1v[8], b2v[8], w3x[8], w3y[8];
        #pragma unroll
        for (int ni = 0; ni < 8; ni++) {
            int j = (colBase + wn + ni * 8 + qcol) >> 1;
            b1v[ni] = b1[j];
            b2v[ni] = b2[j];
            float2 w = reinterpret_cast<const float2*>(W3)[j];
            w3x[ni] = w.x; w3y[ni] = w.y;
        }
        #pragma unroll
        for (int mi = 0; mi < 4; mi++) {
            int r0 = rowBase + wm + mi * 16 + qrow;
            int r1 = r0 + 8;
            float s00 = 0.f, s01 = 0.f, s10 = 0.f, s11 = 0.f;
            #pragma unroll
            for (int ni = 0; ni < 8; ni++) {
                float t1 = acc[mi][ni][0] + b1v[ni];
                float t2 = acc[mi][ni][1] + b2v[ni];
                float a0 = tanhf(t1) * (1.0f / (1.0f + expf(-t2)));
                s00 = fmaf(a0, w3x[ni], s00);
                s01 = fmaf(a0, w3y[ni], s01);
                float u1 = acc[mi][ni][2] + b1v[ni];
                float u2 = acc[mi][ni][3] + b2v[ni];
                float a1 = tanhf(u1) * (1.0f / (1.0f + expf(-u2)));
                s10 = fmaf(a1, w3x[ni], s10);
                s11 = fmaf(a1, w3y[ni], s11);
            }
            #pragma unroll
            for (int o = 1; o <= 2; o <<= 1) {
                s00 += __shfl_xor_sync(0xffffffffu, s00, o);
                s01 += __shfl_xor_sync(0xffffffffu, s01, o);
                s10 += __shfl_xor_sync(0xffffffffu, s10, o);
                s11 += __shfl_xor_sync(0xffffffffu, s11, o);
            }
            if ((lane & 3) == 0) {
                if (r0 < M_BAG) {
                    atomicAdd(&g_att[2 * r0 + 0], s00);
                    atomicAdd(&g_att[2 * r0 + 1], s01);
                }
                if (r1 < M_BAG) {
                    atomicAdd(&g_att[2 * r1 + 0], s10);
                    atomicAdd(&g_att[2 * r1 + 1], s11);
                }
            }
        }
    }
}

// ---------------------------------------------------------------------------
// att finish: add b3, softmax, write att_score / A / A_I
// ---------------------------------------------------------------------------
__global__ void att_finish(const float* __restrict__ b3, const int* __restrict__ sl,
                           float* __restrict__ out)
{
    int r = blockIdx.x * blockDim.x + threadIdx.x;
    if (r >= M_BAG) return;
    float s0 = g_att[2 * r + 0] + b3[0];
    float s1 = g_att[2 * r + 1] + b3[1];
    out[OFF_ATT + 2 * r + 0] = s0;
    out[OFF_ATT + 2 * r + 1] = s1;
    float m  = fmaxf(s0, s1);
    float e0 = expf(s0 - m), e1 = expf(s1 - m);
    float inv = 1.0f / (e0 + e1);
    float A0 = e0 * inv, A1 = e1 * inv;
    out[OFF_A + 2 * r + 0] = A0;
    out[OFF_A + 2 * r + 1] = A1;
    g_AI[r] = (sl[0] != 0) ? A1 : A0;
}

// ---------------------------------------------------------------------------
// slide_agg = A^T @ h (h from fp16 copy), per-block partials + atomics
// ---------------------------------------------------------------------------
__global__ __launch_bounds__(256)
void agg_kernel(const float* __restrict__ Amat)
{
    int tid = threadIdx.x;
    int r0 = blockIdx.x * 256;
    int r1 = min(r0 + 256, M_BAG);

    float a00 = 0.f, a01 = 0.f, a10 = 0.f, a11 = 0.f;
    const __half2* hv2 = reinterpret_cast<const __half2*>(g_hh);
    for (int n = r0; n < r1; n++) {
        float2 Av = reinterpret_cast<const float2*>(Amat)[n];
        __half2 hp = hv2[(size_t)n * 256 + tid];
        float h0 = __low2float(hp), h1 = __high2float(hp);
        a00 = fmaf(Av.x, h0, a00);
        a01 = fmaf(Av.y, h0, a01);
        a10 = fmaf(Av.x, h1, a10);
        a11 = fmaf(Av.y, h1, a11);
    }
    int d0 = tid * 2, d1 = tid * 2 + 1;
    atomicAdd(&g_agg[d0],         a00);
    atomicAdd(&g_agg[NCOMP + d0], a01);
    atomicAdd(&g_agg[d1],         a10);
    atomicAdd(&g_agg[NCOMP + d1], a11);
}

// ---------------------------------------------------------------------------
// Two-stage top-8 / bottom-8, JAX tie-break (lower index wins)
// ---------------------------------------------------------------------------
__global__ __launch_bounds__(256)
void topk_stage1()
{
    __shared__ float svmax[TK_CHUNK];
    __shared__ float svmin[TK_CHUNK];
    __shared__ float rv[256];
    __shared__ int   ri[256];
    int tid  = threadIdx.x;
    int base = blockIdx.x * TK_CHUNK;

    for (int i = tid; i < TK_CHUNK; i += 256) {
        int g = base + i;
        float v = (g < M_BAG) ? g_AI[g] : 0.0f;
        svmax[i] = (g < M_BAG) ? v : -FLT_MAX;
        svmin[i] = (g < M_BAG) ? v :  FLT_MAX;
    }
    __syncthreads();

    for (int pass = 0; pass < 8; pass++) {
        float bv = -FLT_MAX; int bi = 0x7fffffff;
        for (int i = tid; i < TK_CHUNK; i += 256) {
            float v = svmax[i]; int g = base + i;
            if (v > bv || (v == bv && g < bi)) { bv = v; bi = g; }
        }
        rv[tid] = bv; ri[tid] = bi;
        __syncthreads();
        for (int s = 128; s > 0; s >>= 1) {
            if (tid < s) {
                float ov = rv[tid + s]; int oi = ri[tid + s];
                if (ov > rv[tid] || (ov == rv[tid] && oi < ri[tid])) { rv[tid] = ov; ri[tid] = oi; }
            }
            __syncthreads();
        }
        if (tid == 0) {
            g_cmaxv[blockIdx.x * 8 + pass] = rv[0];
            g_cmaxi[blockIdx.x * 8 + pass] = ri[0];
            svmax[ri[0] - base] = -FLT_MAX;
        }
        __syncthreads();
    }
    for (int pass = 0; pass < 8; pass++) {
        float bv = FLT_MAX; int bi = 0x7fffffff;
        for (int i = tid; i < TK_CHUNK; i += 256) {
            float v = svmin[i]; int g = base + i;
            if (v < bv || (v == bv && g < bi)) { bv = v; bi = g; }
        }
        rv[tid] = bv; ri[tid] = bi;
        __syncthreads();
        for (int s = 128; s > 0; s >>= 1) {
            if (tid < s) {
                float ov = rv[tid + s]; int oi = ri[tid + s];
                if (ov < rv[tid] || (ov == rv[tid] && oi < ri[tid])) { rv[tid] = ov; ri[tid] = oi; }
            }
            __syncthreads();
        }
        if (tid == 0) {
            g_cminv[blockIdx.x * 8 + pass] = rv[0];
            g_cmini[blockIdx.x * 8 + pass] = ri[0];
            svmin[ri[0] - base] = FLT_MAX;
        }
        __syncthreads();
    }
}

__global__ __launch_bounds__(512)
void topk_stage2()
{
    __shared__ float sv[512];
    __shared__ int   si[512];
    __shared__ float rv[512];
    __shared__ int   ri[512];
    int tid = threadIdx.x;

    sv[tid] = g_cmaxv[tid];
    si[tid] = g_cmaxi[tid];
    __syncthreads();
    for (int pass = 0; pass < 8; pass++) {
        rv[tid] = sv[tid]; ri[tid] = si[tid];
        __syncthreads();
        for (int s = 256; s > 0; s >>= 1) {
            if (tid < s) {
                float ov = rv[tid + s]; int oi = ri[tid + s];
                if (ov > rv[tid] || (ov == rv[tid] && oi < ri[tid])) { rv[tid] = ov; ri[tid] = oi; }
            }
            __syncthreads();
        }
        if (tid == 0) g_topidx[pass] = ri[0];
        if (si[tid] == ri[0]) { sv[tid] = -FLT_MAX; si[tid] = 0x7fffffff; }
        __syncthreads();
    }
    sv[tid] = g_cminv[tid];
    si[tid] = g_cmini[tid];
    __syncthreads();
    for (int pass = 0; pass < 8; pass++) {
        rv[tid] = sv[tid]; ri[tid] = si[tid];
        __syncthreads();
        for (int s = 256; s > 0; s >>= 1) {
            if (tid < s) {
                float ov = rv[tid + s]; int oi = ri[tid + s];
                if (ov < rv[tid] || (ov == rv[tid] && oi < ri[tid])) { rv[tid] = ov; ri[tid] = oi; }
            }
            __syncthreads();
        }
        if (tid == 0) g_topidx[8 + pass] = ri[0];
        if (si[tid] == ri[0]) { sv[tid] = FLT_MAX; si[tid] = 0x7fffffff; }
        __syncthreads();
    }
}

// ---------------------------------------------------------------------------
// Tail: instance head + slide score
// ---------------------------------------------------------------------------
__global__ __launch_bounds__(1024)
void final_kernel(const float* __restrict__ W_ins, const float* __restrict__ b_ins,
                  const float* __restrict__ W_bag, const float* __restrict__ b_bag,
                  const float* __restrict__ h, float* __restrict__ out)
{
    __shared__ float s_logit[32];
    __shared__ float s_slide[2];
    int tid  = threadIdx.x;
    int lane = tid & 31;
    int w    = tid >> 5;

    {
        int row = w >> 1, c = w & 1;
        int idx = g_topidx[row];
        const float* hr = h + (size_t)idx * NCOMP;
        float acc = 0.f;
        for (int d = lane; d < NCOMP; d += 32)
            acc = fmaf(hr[d], W_ins[2 * d + c], acc);
        #pragma unroll
        for (int o = 16; o > 0; o >>= 1)
            acc += __shfl_xor_sync(0xffffffffu, acc, o);
        if (lane == 0) s_logit[row * 2 + c] = acc + b_ins[c];
    }
    if (w < 2) {
        int c = w;
        float acc = 0.f;
        for (int d = lane; d < NCOMP; d += 32)
            acc = fmaf(g_agg[c * NCOMP + d], W_bag[d], acc);
        #pragma unroll
        for (int o = 16; o > 0; o >>= 1)
            acc += __shfl_xor_sync(0xffffffffu, acc, o);
        if (lane == 0) s_slide[c] = acc + b_bag[0];
    }
    __syncthreads();

    if (tid < 16) {
        float l0 = s_logit[tid * 2 + 0];
        float l1 = s_logit[tid * 2 + 1];
        out[OFF_IU + tid * 2 + 0] = l0;
        out[OFF_IU + tid * 2 + 1] = l1;
        float m = fmaxf(l0, l1);
        float e0 = expf(l0 - m), e1 = expf(l1 - m);
        float inv = 1.0f / (e0 + e1);
        out[OFF_IL + tid * 2 + 0] = e0 * inv;
        out[OFF_IL + tid * 2 + 1] = e1 * inv;
        out[OFF_LAB + tid] = (tid < 8) ? 1.0f : 0.0f;
    }
    if (tid == 0) {
        float s0 = s_slide[0], s1 = s_slide[1];
        out[OFF_SS + 0] = s0;
        out[OFF_SS + 1] = s1;
        float m = fmaxf(s0, s1);
        float e0 = expf(s0 - m), e1 = expf(s1 - m);
        float inv = 1.0f / (e0 + e1);
        out[OFF_YP + 0] = e0 * inv;
        out[OFF_YP + 1] = e1 * inv;
        out[OFF_YH] = (s1 > s0) ? 1.0f : 0.0f;
    }
}

// ---------------------------------------------------------------------------
// kernel_launch
// ---------------------------------------------------------------------------
extern "C" void kernel_launch(void* const* d_in, const int* in_sizes, int n_in,
                              void* d_out, int out_size)
{
    const float* x   = (const float*)d_in[0];
    const int*   sl  = (const int*)  d_in[1];
    const float* Wc  = (const float*)d_in[2];
    const float* bc  = (const float*)d_in[3];
    const float* W1  = (const float*)d_in[4];
    const float* b1  = (const float*)d_in[5];
    const float* W2  = (const float*)d_in[6];
    const float* b2  = (const float*)d_in[7];
    const float* W3  = (const float*)d_in[8];
    const float* b3  = (const float*)d_in[9];
    const float* Wi  = (const float*)d_in[10];
    const float* bi  = (const float*)d_in[11];
    const float* Wb  = (const float*)d_in[12];
    const float* bb  = (const float*)d_in[13];

    float* out = (float*)d_out;
    float* h   = out + OFF_H;

    const int SMEM0 = 2 * (128 * 128 + 256 * 128);   // 96 KB
    const int SMEM1 = 2 * (64 * 128 + 512 * 128);    // 144 KB
    cudaFuncSetAttribute(hmma_gemm<0>, cudaFuncAttributeMaxDynamicSharedMemorySize, SMEM0);
    cudaFuncSetAttribute(hmma_gemm<1>, cudaFuncAttributeMaxDynamicSharedMemorySize, SMEM1);

    prep_weights<<<3072, 256>>>(Wc, W1, W2);
    zero_init<<<(2 * M_BAG + 255) / 256, 256>>>();

    // h = relu(x @ Wc + bc), conversion fused into A loader
    hmma_gemm<0><<<dim3(2, M_PAD / 128), 256, SMEM0>>>(x, bc, b1, b2, W3, out);

    // gated attention GEMM, full N=512 per CTA (h read once)
    hmma_gemm<1><<<dim3(1, M_PAD / 64), 256, SMEM1>>>(x, bc, b1, b2, W3, out);

    att_finish<<<(M_BAG + 255) / 256, 256>>>(b3, sl, out);

    agg_kernel<<<(M_BAG + 255) / 256, 256>>>(out + OFF_A);

    topk_stage1<<<TK_BLOCKS, 256>>>();
    topk_stage2<<<1, 512>>>();

    final_kernel<<<1, 1024>>>(Wi, bi, Wb, bb, h, out);
}

// round 6
// speedup vs baseline: 6.3462x; 1.0930x over previous
#include <cuda_runtime.h>
#include <cuda_fp16.h>
#include <math.h>
#include <float.h>
#include <stdint.h>

// ---------------------------------------------------------------------------
// Problem constants
// ---------------------------------------------------------------------------
#define M_BAG   100000
#define M_PAD   100096          // 782 * 128
#define NFEAT   1024
#define NCOMP   512
#define NHID    256

// Output layout (flattened reference tuple, fp32)
#define OFF_ATT   0u
#define OFF_A     200000u
#define OFF_H     400000u
#define OFF_LAB   51600000u
#define OFF_IU    51600016u
#define OFF_IL    51600048u
#define OFF_SS    51600080u
#define OFF_YP    51600082u
#define OFF_YH    51600084u

// ---------------------------------------------------------------------------
// Device scratch (static globals; allocation-free per harness rules)
// ---------------------------------------------------------------------------
__device__ __half g_hh[(size_t)M_PAD * NCOMP];    // h in fp16 (padded rows zero)
__device__ __half g_Wct[(size_t)NCOMP * NFEAT];   // Wc^T  [512][1024]
__device__ __half g_Wt12[(size_t)NCOMP * NCOMP];  // interleaved [W1|W2]^T [512][512]
__device__ float  g_att[2 * M_BAG];               // unnormalized att (atomic acc)
__device__ float  g_AI[M_BAG];
__device__ float  g_agg[2 * NCOMP];
__device__ int    g_topidx[16];
#define TK_BLOCKS 64
#define TK_CHUNK  1568
__device__ float  g_cmaxv[TK_BLOCKS * 8];
__device__ int    g_cmaxi[TK_BLOCKS * 8];
__device__ float  g_cminv[TK_BLOCKS * 8];
__device__ int    g_cmini[TK_BLOCKS * 8];

// ---------------------------------------------------------------------------
// PTX helpers (sm_80+ features only: mma.sync / ldmatrix / cp.async)
// ---------------------------------------------------------------------------
__device__ __forceinline__ uint32_t smem_u32(const void* p) {
    uint32_t a;
    asm("{ .reg .u64 t; cvta.to.shared.u64 t, %1; cvt.u32.u64 %0, t; }"
        : "=r"(a) : "l"(p));
    return a;
}

#define CPASYNC16(sa, gp) \
    asm volatile("cp.async.cg.shared.global [%0], [%1], 16;" \
                 :: "r"(sa), "l"(gp))
#define CPCOMMIT() asm volatile("cp.async.commit_group;")
template<int N> __device__ __forceinline__ void cp_wait() {
    asm volatile("cp.async.wait_group %0;" :: "n"(N));
}

__device__ __forceinline__ void ldsm4(uint32_t& r0, uint32_t& r1,
                                      uint32_t& r2, uint32_t& r3, uint32_t a) {
    asm volatile("ldmatrix.sync.aligned.m8n8.x4.shared.b16 {%0,%1,%2,%3}, [%4];"
                 : "=r"(r0), "=r"(r1), "=r"(r2), "=r"(r3) : "r"(a));
}

__device__ __forceinline__ void mma16816(float* c, const uint32_t* a,
                                         uint32_t b0, uint32_t b1) {
    asm volatile(
        "mma.sync.aligned.m16n8k16.row.col.f32.f16.f16.f32 "
        "{%0,%1,%2,%3}, {%4,%5,%6,%7}, {%8,%9}, {%0,%1,%2,%3};"
        : "+f"(c[0]), "+f"(c[1]), "+f"(c[2]), "+f"(c[3])
        : "r"(a[0]), "r"(a[1]), "r"(a[2]), "r"(a[3]), "r"(b0), "r"(b1));
}

__device__ __forceinline__ float tanha(float x) {
    float y; asm("tanh.approx.f32 %0, %1;" : "=f"(y) : "f"(x)); return y;
}

// ---------------------------------------------------------------------------
// Prep: Wc^T -> fp16, interleaved [W1|W2]^T -> fp16
// ---------------------------------------------------------------------------
__global__ void prep_weights(const float* __restrict__ Wc,
                             const float* __restrict__ W1,
                             const float* __restrict__ W2)
{
    int i = blockIdx.x * blockDim.x + threadIdx.x;
    const int T1 = NCOMP * NFEAT;           // 524288
    if (i < T1) {
        int n = i / NFEAT, k = i % NFEAT;
        g_Wct[i] = __float2half_rn(Wc[(size_t)k * NCOMP + n]);
    }
    int i2 = i - T1;
    if (i2 >= 0 && i2 < NCOMP * NCOMP) {
        int rowN = i2 / NCOMP, k = i2 % NCOMP;
        int j = rowN >> 1, p = rowN & 1;
        const float* W = p ? W2 : W1;
        g_Wt12[i2] = __float2half_rn(W[(size_t)k * NHID + j]);
    }
}

__global__ void zero_init()
{
    int i = blockIdx.x * blockDim.x + threadIdx.x;
    if (i < 2 * M_BAG)  g_att[i] = 0.0f;
    if (i < 2 * NCOMP)  g_agg[i] = 0.0f;
}

// ---------------------------------------------------------------------------
// HMMA GEMM: BM=128, BN=256, 256 threads (8 warps, 2x4 of 64x64),
// 3-stage pipeline (48KB/stage), SW128 swizzle.
// MODE 0: K=1024. h = relu(x @ Wc + bc); A = fp32 LDG -> reg convert -> STS.
//         Epilogue writes h fp32 (out) + fp16 (g_hh).
// MODE 1: K=512.  t = h @ [W1|W2] interleaved; A,B via cp.async.
//         Epilogue: a = tanh(t1)*sigmoid(t2) (MUFU approx), a@W3 -> g_att.
// ---------------------------------------------------------------------------
template<int MODE>
__global__ void __launch_bounds__(256)
hmma_gemm(const float* __restrict__ x, const float* __restrict__ bc,
          const float* __restrict__ b1, const float* __restrict__ b2,
          const float* __restrict__ W3, float* __restrict__ out)
{
    constexpr int K      = (MODE == 0) ? NFEAT : NCOMP;
    constexpr int NT     = K / 64;
    constexpr int ABYTES = 128 * 128;               // 16 KB
    constexpr int STRIDE = ABYTES + 256 * 128;      // 48 KB / stage

    extern __shared__ __align__(1024) char smem[];

    const int tid  = threadIdx.x;
    const int lane = tid & 31;
    const int wid  = tid >> 5;
    const int wm   = (wid >> 2) * 64;
    const int wn   = (wid & 3) * 64;
    const int rowBase = blockIdx.y * 128;
    const int colBase = blockIdx.x * 256;

    const uint32_t sbase = smem_u32(smem);
    const __half* Aglob = (MODE == 0) ? (const __half*)nullptr : g_hh;
    const __half* Bglob = (MODE == 0) ? g_Wct : g_Wt12;

    // ldmatrix lane constants
    const int aRowOff = (lane & 7) + ((lane >> 3) & 1) * 8;
    const int aCk     = (lane >> 4) & 1;
    const int bRowOff = (lane & 7) + ((lane >> 4) & 1) * 8;
    const int bCk     = (lane >> 3) & 1;

    float acc[4][8][4];
    #pragma unroll
    for (int mi = 0; mi < 4; mi++)
        #pragma unroll
        for (int ni = 0; ni < 8; ni++)
            #pragma unroll
            for (int q = 0; q < 4; q++) acc[mi][ni][q] = 0.0f;

    // ---- loaders -----------------------------------------------------------
    auto load_b = [&](int kt, int stg) {
        const uint32_t sB = sbase + stg * STRIDE + ABYTES;
        const __half* Bg = Bglob + (size_t)colBase * K + kt * 64;
        #pragma unroll
        for (int i = 0; i < 8; i++) {
            int lin = tid + 256 * i;
            int row = lin >> 3, seg = lin & 7;
            uint32_t sa = sB + row * 128 + ((seg ^ (row & 7)) << 4);
            CPASYNC16(sa, Bg + (size_t)row * K + seg * 8);
        }
    };
    auto cp_a = [&](int kt, int stg) {      // MODE 1
        const uint32_t sA = sbase + stg * STRIDE;
        const __half* Ag = Aglob + (size_t)rowBase * K + kt * 64;
        #pragma unroll
        for (int i = 0; i < 4; i++) {
            int lin = tid + 256 * i;
            int row = lin >> 3, seg = lin & 7;
            uint32_t sa = sA + row * 128 + ((seg ^ (row & 7)) << 4);
            CPASYNC16(sa, Ag + (size_t)row * K + seg * 8);
        }
    };

    float4 areg[8];                          // MODE 0: fp32 A prefetch
    auto ldg_a = [&](int kt) {
        #pragma unroll
        for (int i = 0; i < 4; i++) {
            int lin = tid + 256 * i;
            int row = lin >> 3, seg = lin & 7;
            int gr  = rowBase + row;
            if (gr < M_BAG) {
                const float4* p = reinterpret_cast<const float4*>(
                    x + (size_t)gr * K + kt * 64 + seg * 8);
                areg[2 * i]     = p[0];
                areg[2 * i + 1] = p[1];
            } else {
                areg[2 * i]     = make_float4(0.f, 0.f, 0.f, 0.f);
                areg[2 * i + 1] = make_float4(0.f, 0.f, 0.f, 0.f);
            }
        }
    };
    auto sts_a = [&](int stg) {              // MODE 0
        char* sA = smem + stg * STRIDE;
        #pragma unroll
        for (int i = 0; i < 4; i++) {
            int lin = tid + 256 * i;
            int row = lin >> 3, seg = lin & 7;
            float4 a = areg[2 * i], b = areg[2 * i + 1];
            __half2 h0 = __floats2half2_rn(a.x, a.y);
            __half2 h1 = __floats2half2_rn(a.z, a.w);
            __half2 h2 = __floats2half2_rn(b.x, b.y);
            __half2 h3 = __floats2half2_rn(b.z, b.w);
            uint4 v;
            v.x = *reinterpret_cast<uint32_t*>(&h0);
            v.y = *reinterpret_cast<uint32_t*>(&h1);
            v.z = *reinterpret_cast<uint32_t*>(&h2);
            v.w = *reinterpret_cast<uint32_t*>(&h3);
            *reinterpret_cast<uint4*>(sA + row * 128 + ((seg ^ (row & 7)) << 4)) = v;
        }
    };

    // ---- prologue: stages 0 and 1 -----------------------------------------
    if (MODE == 0) {
        ldg_a(0); load_b(0, 0); CPCOMMIT(); sts_a(0);
        ldg_a(1); load_b(1, 1); CPCOMMIT(); sts_a(1);
    } else {
        cp_a(0, 0); load_b(0, 0); CPCOMMIT();
        cp_a(1, 1); load_b(1, 1); CPCOMMIT();
    }

    // ---- main loop: 3-stage rotation --------------------------------------
    for (int kt = 0; kt < NT; kt++) {
        if (kt == NT - 1) cp_wait<0>(); else cp_wait<1>();
        __syncthreads();

        const bool pre = (kt + 2 < NT);
        const int  nstg = (kt + 2) % 3;
        if (pre) {
            if (MODE == 0) {
                ldg_a(kt + 2);
                load_b(kt + 2, nstg);
            } else {
                cp_a(kt + 2, nstg);
                load_b(kt + 2, nstg);
            }
            CPCOMMIT();
        }

        const uint32_t sA = sbase + (kt % 3) * STRIDE;
        const uint32_t sB = sA + ABYTES;

        #pragma unroll
        for (int ks = 0; ks < 4; ks++) {
            uint32_t a[4][4];
            #pragma unroll
            for (int mi = 0; mi < 4; mi++) {
                int row = wm + mi * 16 + aRowOff;
                uint32_t ad = sA + row * 128 +
                              (((ks * 2 + aCk) ^ (row & 7)) << 4);
                ldsm4(a[mi][0], a[mi][1], a[mi][2], a[mi][3], ad);
            }
            #pragma unroll
            for (int np = 0; np < 4; np++) {
                uint32_t b0, b1r, b2r, b3r;
                int row = wn + np * 16 + bRowOff;
                uint32_t bd = sB + row * 128 +
                              (((ks * 2 + bCk) ^ (row & 7)) << 4);
                ldsm4(b0, b1r, b2r, b3r, bd);
                #pragma unroll
                for (int mi = 0; mi < 4; mi++) {
                    mma16816(acc[mi][2 * np + 0], a[mi], b0, b1r);
                    mma16816(acc[mi][2 * np + 1], a[mi], b2r, b3r);
                }
            }
        }

        if (MODE == 0 && pre) sts_a(nstg);
    }

    // ------------------------ epilogue ------------------------
    const int qrow = lane >> 2;          // 0..7
    const int qcol = (lane & 3) * 2;     // 0,2,4,6

    if (MODE == 0) {
        float* h32 = out + OFF_H;
        float2 bias_v[8];
        #pragma unroll
        for (int ni = 0; ni < 8; ni++) {
            int col = colBase + wn + ni * 8 + qcol;
            bias_v[ni] = *reinterpret_cast<const float2*>(bc + col);
        }
        #pragma unroll
        for (int mi = 0; mi < 4; mi++) {
            int r0 = rowBase + wm + mi * 16 + qrow;
            int r1 = r0 + 8;
            #pragma unroll
            for (int ni = 0; ni < 8; ni++) {
                int col = colBase + wn + ni * 8 + qcol;
                float v0 = fmaxf(acc[mi][ni][0] + bias_v[ni].x, 0.f);
                float v1 = fmaxf(acc[mi][ni][1] + bias_v[ni].y, 0.f);
                float v2 = fmaxf(acc[mi][ni][2] + bias_v[ni].x, 0.f);
                float v3 = fmaxf(acc[mi][ni][3] + bias_v[ni].y, 0.f);
                if (r0 < M_BAG) {
                    *reinterpret_cast<float2*>(h32 + (size_t)r0 * NCOMP + col)
                        = make_float2(v0, v1);
                    __half2 p = __floats2half2_rn(v0, v1);
                    *reinterpret_cast<__half2*>(g_hh + (size_t)r0 * NCOMP + col) = p;
                }
                if (r1 < M_BAG) {
                    *reinterpret_cast<float2*>(h32 + (size_t)r1 * NCOMP + col)
                        = make_float2(v2, v3);
                    __half2 p = __floats2half2_rn(v2, v3);
                    *reinterpret_cast<__half2*>(g_hh + (size_t)r1 * NCOMP + col) = p;
                }
            }
        }
    } else {
        // gate (MUFU approx) + a@W3, quad-reduced atomics
        float b1v[8], b2v[8], w3x[8], w3y[8];
        #pragma unroll
        for (int ni = 0; ni < 8; ni++) {
            int j = (colBase + wn + ni * 8 + qcol) >> 1;
            b1v[ni] = b1[j];
            b2v[ni] = b2[j];
            float2 w = reinterpret_cast<const float2*>(W3)[j];
            w3x[ni] = w.x; w3y[ni] = w.y;
        }
        #pragma unroll
        for (int mi = 0; mi < 4; mi++) {
            int r0 = rowBase + wm + mi * 16 + qrow;
            int r1 = r0 + 8;
            float s00 = 0.f, s01 = 0.f, s10 = 0.f, s11 = 0.f;
            #pragma unroll
            for (int ni = 0; ni < 8; ni++) {
                float t1 = acc[mi][ni][0] + b1v[ni];
                float t2 = acc[mi][ni][1] + b2v[ni];
                float a0 = tanha(t1) * fmaf(tanha(0.5f * t2), 0.5f, 0.5f);
                s00 = fmaf(a0, w3x[ni], s00);
                s01 = fmaf(a0, w3y[ni], s01);
                float u1 = acc[mi][ni][2] + b1v[ni];
                float u2 = acc[mi][ni][3] + b2v[ni];
                float a1 = tanha(u1) * fmaf(tanha(0.5f * u2), 0.5f, 0.5f);
                s10 = fmaf(a1, w3x[ni], s10);
                s11 = fmaf(a1, w3y[ni], s11);
            }
            #pragma unroll
            for (int o = 1; o <= 2; o <<= 1) {
                s00 += __shfl_xor_sync(0xffffffffu, s00, o);
                s01 += __shfl_xor_sync(0xffffffffu, s01, o);
                s10 += __shfl_xor_sync(0xffffffffu, s10, o);
                s11 += __shfl_xor_sync(0xffffffffu, s11, o);
            }
            if ((lane & 3) == 0) {
                if (r0 < M_BAG) {
                    atomicAdd(&g_att[2 * r0 + 0], s00);
                    atomicAdd(&g_att[2 * r0 + 1], s01);
                }
                if (r1 < M_BAG) {
                    atomicAdd(&g_att[2 * r1 + 0], s10);
                    atomicAdd(&g_att[2 * r1 + 1], s11);
                }
            }
        }
    }
}

// ---------------------------------------------------------------------------
// att finish: add b3, softmax, write att_score / A / A_I
// ---------------------------------------------------------------------------
__global__ void att_finish(const float* __restrict__ b3, const int* __restrict__ sl,
                           float* __restrict__ out)
{
    int r = blockIdx.x * blockDim.x + threadIdx.x;
    if (r >= M_BAG) return;
    float s0 = g_att[2 * r + 0] + b3[0];
    float s1 = g_att[2 * r + 1] + b3[1];
    out[OFF_ATT + 2 * r + 0] = s0;
    out[OFF_ATT + 2 * r + 1] = s1;
    float m  = fmaxf(s0, s1);
    float e0 = expf(s0 - m), e1 = expf(s1 - m);
    float inv = 1.0f / (e0 + e1);
    float A0 = e0 * inv, A1 = e1 * inv;
    out[OFF_A + 2 * r + 0] = A0;
    out[OFF_A + 2 * r + 1] = A1;
    g_AI[r] = (sl[0] != 0) ? A1 : A0;
}

// ---------------------------------------------------------------------------
// slide_agg = A^T @ h (h from fp16 copy), per-block partials + atomics
// ---------------------------------------------------------------------------
__global__ __launch_bounds__(256)
void agg_kernel(const float* __restrict__ Amat)
{
    int tid = threadIdx.x;
    int r0 = blockIdx.x * 256;
    int r1 = min(r0 + 256, M_BAG);

    float a00 = 0.f, a01 = 0.f, a10 = 0.f, a11 = 0.f;
    const __half2* hv2 = reinterpret_cast<const __half2*>(g_hh);
    for (int n = r0; n < r1; n++) {
        float2 Av = reinterpret_cast<const float2*>(Amat)[n];
        __half2 hp = hv2[(size_t)n * 256 + tid];
        float h0 = __low2float(hp), h1 = __high2float(hp);
        a00 = fmaf(Av.x, h0, a00);
        a01 = fmaf(Av.y, h0, a01);
        a10 = fmaf(Av.x, h1, a10);
        a11 = fmaf(Av.y, h1, a11);
    }
    int d0 = tid * 2, d1 = tid * 2 + 1;
    atomicAdd(&g_agg[d0],         a00);
    atomicAdd(&g_agg[NCOMP + d0], a01);
    atomicAdd(&g_agg[d1],         a10);
    atomicAdd(&g_agg[NCOMP + d1], a11);
}

// ---------------------------------------------------------------------------
// Two-stage top-8 / bottom-8, JAX tie-break (lower index wins)
// ---------------------------------------------------------------------------
__global__ __launch_bounds__(256)
void topk_stage1()
{
    __shared__ float svmax[TK_CHUNK];
    __shared__ float svmin[TK_CHUNK];
    __shared__ float rv[256];
    __shared__ int   ri[256];
    int tid  = threadIdx.x;
    int base = blockIdx.x * TK_CHUNK;

    for (int i = tid; i < TK_CHUNK; i += 256) {
        int g = base + i;
        float v = (g < M_BAG) ? g_AI[g] : 0.0f;
        svmax[i] = (g < M_BAG) ? v : -FLT_MAX;
        svmin[i] = (g < M_BAG) ? v :  FLT_MAX;
    }
    __syncthreads();

    for (int pass = 0; pass < 8; pass++) {
        float bv = -FLT_MAX; int bi = 0x7fffffff;
        for (int i = tid; i < TK_CHUNK; i += 256) {
            float v = svmax[i]; int g = base + i;
            if (v > bv || (v == bv && g < bi)) { bv = v; bi = g; }
        }
        rv[tid] = bv; ri[tid] = bi;
        __syncthreads();
        for (int s = 128; s > 0; s >>= 1) {
            if (tid < s) {
                float ov = rv[tid + s]; int oi = ri[tid + s];
                if (ov > rv[tid] || (ov == rv[tid] && oi < ri[tid])) { rv[tid] = ov; ri[tid] = oi; }
            }
            __syncthreads();
        }
        if (tid == 0) {
            g_cmaxv[blockIdx.x * 8 + pass] = rv[0];
            g_cmaxi[blockIdx.x * 8 + pass] = ri[0];
            svmax[ri[0] - base] = -FLT_MAX;
        }
        __syncthreads();
    }
    for (int pass = 0; pass < 8; pass++) {
        float bv = FLT_MAX; int bi = 0x7fffffff;
        for (int i = tid; i < TK_CHUNK; i += 256) {
            float v = svmin[i]; int g = base + i;
            if (v < bv || (v == bv && g < bi)) { bv = v; bi = g; }
        }
        rv[tid] = bv; ri[tid] = bi;
        __syncthreads();
        for (int s = 128; s > 0; s >>= 1) {
            if (tid < s) {
                float ov = rv[tid + s]; int oi = ri[tid + s];
                if (ov < rv[tid] || (ov == rv[tid] && oi < ri[tid])) { rv[tid] = ov; ri[tid] = oi; }
            }
            __syncthreads();
        }
        if (tid == 0) {
            g_cminv[blockIdx.x * 8 + pass] = rv[0];
            g_cmini[blockIdx.x * 8 + pass] = ri[0];
            svmin[ri[0] - base] = FLT_MAX;
        }
        __syncthreads();
    }
}

__global__ __launch_bounds__(512)
void topk_stage2()
{
    __shared__ float sv[512];
    __shared__ int   si[512];
    __shared__ float rv[512];
    __shared__ int   ri[512];
    int tid = threadIdx.x;

    sv[tid] = g_cmaxv[tid];
    si[tid] = g_cmaxi[tid];
    __syncthreads();
    for (int pass = 0; pass < 8; pass++) {
        rv[tid] = sv[tid]; ri[tid] = si[tid];
        __syncthreads();
        for (int s = 256; s > 0; s >>= 1) {
            if (tid < s) {
                float ov = rv[tid + s]; int oi = ri[tid + s];
                if (ov > rv[tid] || (ov == rv[tid] && oi < ri[tid])) { rv[tid] = ov; ri[tid] = oi; }
            }
            __syncthreads();
        }
        if (tid == 0) g_topidx[pass] = ri[0];
        if (si[tid] == ri[0]) { sv[tid] = -FLT_MAX; si[tid] = 0x7fffffff; }
        __syncthreads();
    }
    sv[tid] = g_cminv[tid];
    si[tid] = g_cmini[tid];
    __syncthreads();
    for (int pass = 0; pass < 8; pass++) {
        rv[tid] = sv[tid]; ri[tid] = si[tid];
        __syncthreads();
        for (int s = 256; s > 0; s >>= 1) {
            if (tid < s) {
                float ov = rv[tid + s]; int oi = ri[tid + s];
                if (ov < rv[tid] || (ov == rv[tid] && oi < ri[tid])) { rv[tid] = ov; ri[tid] = oi; }
            }
            __syncthreads();
        }
        if (tid == 0) g_topidx[8 + pass] = ri[0];
        if (si[tid] == ri[0]) { sv[tid] = FLT_MAX; si[tid] = 0x7fffffff; }
        __syncthreads();
    }
}

// ---------------------------------------------------------------------------
// Tail: instance head + slide score
// ---------------------------------------------------------------------------
__global__ __launch_bounds__(1024)
void final_kernel(const float* __restrict__ W_ins, const float* __restrict__ b_ins,
                  const float* __restrict__ W_bag, const float* __restrict__ b_bag,
                  const float* __restrict__ h, float* __restrict__ out)
{
    __shared__ float s_logit[32];
    __shared__ float s_slide[2];
    int tid  = threadIdx.x;
    int lane = tid & 31;
    int w    = tid >> 5;

    {
        int row = w >> 1, c = w & 1;
        int idx = g_topidx[row];
        const float* hr = h + (size_t)idx * NCOMP;
        float acc = 0.f;
        for (int d = lane; d < NCOMP; d += 32)
            acc = fmaf(hr[d], W_ins[2 * d + c], acc);
        #pragma unroll
        for (int o = 16; o > 0; o >>= 1)
            acc += __shfl_xor_sync(0xffffffffu, acc, o);
        if (lane == 0) s_logit[row * 2 + c] = acc + b_ins[c];
    }
    if (w < 2) {
        int c = w;
        float acc = 0.f;
        for (int d = lane; d < NCOMP; d += 32)
            acc = fmaf(g_agg[c * NCOMP + d], W_bag[d], acc);
        #pragma unroll
        for (int o = 16; o > 0; o >>= 1)
            acc += __shfl_xor_sync(0xffffffffu, acc, o);
        if (lane == 0) s_slide[c] = acc + b_bag[0];
    }
    __syncthreads();

    if (tid < 16) {
        float l0 = s_logit[tid * 2 + 0];
        float l1 = s_logit[tid * 2 + 1];
        out[OFF_IU + tid * 2 + 0] = l0;
        out[OFF_IU + tid * 2 + 1] = l1;
        float m = fmaxf(l0, l1);
        float e0 = expf(l0 - m), e1 = expf(l1 - m);
        float inv = 1.0f / (e0 + e1);
        out[OFF_IL + tid * 2 + 0] = e0 * inv;
        out[OFF_IL + tid * 2 + 1] = e1 * inv;
        out[OFF_LAB + tid] = (tid < 8) ? 1.0f : 0.0f;
    }
    if (tid == 0) {
        float s0 = s_slide[0], s1 = s_slide[1];
        out[OFF_SS + 0] = s0;
        out[OFF_SS + 1] = s1;
        float m = fmaxf(s0, s1);
        float e0 = expf(s0 - m), e1 = expf(s1 - m);
        float inv = 1.0f / (e0 + e1);
        out[OFF_YP + 0] = e0 * inv;
        out[OFF_YP + 1] = e1 * inv;
        out[OFF_YH] = (s1 > s0) ? 1.0f : 0.0f;
    }
}

// ---------------------------------------------------------------------------
// kernel_launch
// ---------------------------------------------------------------------------
extern "C" void kernel_launch(void* const* d_in, const int* in_sizes, int n_in,
                              void* d_out, int out_size)
{
    const float* x   = (const float*)d_in[0];
    const int*   sl  = (const int*)  d_in[1];
    const float* Wc  = (const float*)d_in[2];
    const float* bc  = (const float*)d_in[3];
    const float* W1  = (const float*)d_in[4];
    const float* b1  = (const float*)d_in[5];
    const float* W2  = (const float*)d_in[6];
    const float* b2  = (const float*)d_in[7];
    const float* W3  = (const float*)d_in[8];
    const float* b3  = (const float*)d_in[9];
    const float* Wi  = (const float*)d_in[10];
    const float* bi  = (const float*)d_in[11];
    const float* Wb  = (const float*)d_in[12];
    const float* bb  = (const float*)d_in[13];

    float* out = (float*)d_out;
    float* h   = out + OFF_H;

    const int SMEM = 3 * (128 * 128 + 256 * 128);   // 144 KB
    cudaFuncSetAttribute(hmma_gemm<0>, cudaFuncAttributeMaxDynamicSharedMemorySize, SMEM);
    cudaFuncSetAttribute(hmma_gemm<1>, cudaFuncAttributeMaxDynamicSharedMemorySize, SMEM);

    prep_weights<<<3072, 256>>>(Wc, W1, W2);
    zero_init<<<(2 * M_BAG + 255) / 256, 256>>>();

    // h = relu(x @ Wc + bc), fp32->fp16 conversion fused into A loader
    hmma_gemm<0><<<dim3(2, M_PAD / 128), 256, SMEM>>>(x, bc, b1, b2, W3, out);

    // gated attention GEMM (interleaved W1|W2), fused gate + a@W3 epilogue
    hmma_gemm<1><<<dim3(2, M_PAD / 128), 256, SMEM>>>(x, bc, b1, b2, W3, out);

    att_finish<<<(M_BAG + 255) / 256, 256>>>(b3, sl, out);

    agg_kernel<<<(M_BAG + 255) / 256, 256>>>(out + OFF_A);

    topk_stage1<<<TK_BLOCKS, 256>>>();
    topk_stage2<<<1, 512>>>();

    final_kernel<<<1, 1024>>>(Wi, bi, Wb, bb, h, out);
}